// round 11
// baseline (speedup 1.0000x reference)
#include <cuda_runtime.h>
#include <cstdint>

// ---------------------------------------------------------------------------
// Arch feature gate: tcgen05 only exists on the sm_103a/sm_100a targets.
// The harness also assembles a plain compute_103 PTX — that pass gets the
// fp32 fallback bodies below (same kernel symbols, same launcher).
// ---------------------------------------------------------------------------
#if defined(__CUDA_ARCH__) && defined(__CUDA_ARCH_HAS_FEATURE__)
#  if __CUDA_ARCH_HAS_FEATURE__(SM103_ALL) || __CUDA_ARCH_HAS_FEATURE__(SM100_ALL)
#    define USE_TCGEN05 1
#  endif
#endif
#ifndef USE_TCGEN05
#  define USE_TCGEN05 0
#endif

// ---------------------------------------------------------------------------
// Problem constants
// ---------------------------------------------------------------------------
#define B_    128
#define DV_   2048
#define S_    196
#define DQ_   2048
#define DA_   1200
#define G_    4
#define DH_   2048
#define DHG_  512
#define NANS_ 3000
#define M_MAIN (B_ * S_)       // 25088
#define NSLOT_MAIN 10          // 5 N-blocks x 2 col-halves

// ---------------------------------------------------------------------------
// Static scratch (no cudaMalloc allowed)
// ---------------------------------------------------------------------------
__device__ float g_At[(size_t)M_MAIN * DV_];        // [B*S, DV] tf32-rounded
__device__ float g_Bt_v[(size_t)DA_ * DV_];         // Wv_att^T   [1200,2048]
__device__ float g_Bt_qatt[(size_t)DA_ * DQ_];      // Wq_att^T   [1200,2048]
__device__ float g_Bt_qf[(size_t)DH_ * DQ_];        // Wqf^T      [2048,2048]
__device__ float g_Bt_c[(size_t)NANS_ * DH_];       // Wc^T       [3000,2048]
__device__ float g_Bt_f[(size_t)G_ * DHG_ * DV_];   // Wf^T per g [4,512,2048]
__device__ float g_qr[B_ * DQ_];                    // tf32-rounded q
__device__ float g_xq_att[B_ * DA_];
__device__ float g_spart[(size_t)NSLOT_MAIN * M_MAIN * G_]; // score partials
__device__ float g_scores[M_MAIN * G_];
__device__ float g_att[M_MAIN * G_];
__device__ float g_vatt[B_ * G_ * DV_];
__device__ float g_xv[B_ * DH_];
__device__ float g_xqf[B_ * DH_];
__device__ float g_xfused[B_ * DH_];

// ---------------------------------------------------------------------------
// Common helpers
// ---------------------------------------------------------------------------
__device__ __forceinline__ float to_tf32(float x) {
    float r;
    asm("cvt.rna.tf32.f32 %0, %1;" : "=f"(r) : "f"(x));
    return r;
}

#if USE_TCGEN05
// ---------------------------------------------------------------------------
// PTX helpers (sm_103a only)
// ---------------------------------------------------------------------------
__device__ __forceinline__ uint32_t smem_u32(const void* p) {
    uint32_t a;
    asm("{ .reg .u64 t; cvta.to.shared.u64 t, %1; cvt.u32.u64 %0, t; }"
        : "=r"(a) : "l"(p));
    return a;
}
__device__ __forceinline__ uint32_t elect_one() {
    uint32_t pred;
    asm volatile("{ .reg .pred p; elect.sync _|p, 0xFFFFFFFF; selp.b32 %0, 1, 0, p; }"
                 : "=r"(pred));
    return pred;
}

#define MBARRIER_INIT(addr, cnt) \
    asm volatile("mbarrier.init.shared.b64 [%0], %1;" :: "r"(addr), "r"(cnt) : "memory")

#define MBARRIER_WAIT_PARITY(addr, par) do {                                        \
    uint32_t _m = (addr), _p = (par), _d;                                           \
    asm volatile("{ .reg .pred p; mbarrier.try_wait.parity.acquire.cta.shared::cta.b64 p, [%1], %2;" \
                 " selp.b32 %0, 1, 0, p; }" : "=r"(_d) : "r"(_m), "r"(_p) : "memory"); \
    if (!_d) {                                                                      \
        asm volatile("{ .reg .pred P1;\n"                                           \
            "W_%=: mbarrier.try_wait.parity.acquire.cta.shared::cta.b64 P1, [%0], %1, 0x989680;\n" \
            "@P1 bra.uni D_%=;\n bra.uni W_%=;\n D_%=: }"                           \
            :: "r"(_m), "r"(_p) : "memory");                                        \
    }                                                                               \
} while (0)

#define TCGEN05_ALLOC(smem_addr, n) \
    asm volatile("tcgen05.alloc.cta_group::1.sync.aligned.shared::cta.b32 [%0], %1;" \
                 :: "r"(smem_addr), "r"((uint32_t)(n)) : "memory")
#define TCGEN05_RELINQ() \
    asm volatile("tcgen05.relinquish_alloc_permit.cta_group::1.sync.aligned;")
#define TCGEN05_DEALLOC(tmem, n) \
    asm volatile("tcgen05.dealloc.cta_group::1.sync.aligned.b32 %0, %1;" :: "r"(tmem), "r"((uint32_t)(n)))
#define TCGEN05_COMMIT(mbar) \
    asm volatile("tcgen05.commit.cta_group::1.mbarrier::arrive::one.shared::cluster.b64 [%0];" \
                 :: "r"(mbar) : "memory")
#define TCGEN05_WAIT_LD() asm volatile("tcgen05.wait::ld.sync.aligned;" ::: "memory")
#define TCGEN05_FENCE_AFTER() asm volatile("tcgen05.fence::after_thread_sync;" ::: "memory")

#define TCGEN05_LD_X32(r, addr) \
    asm volatile("tcgen05.ld.sync.aligned.32x32b.x32.b32 " \
        "{%0,%1,%2,%3,%4,%5,%6,%7,%8,%9,%10,%11,%12,%13,%14,%15," \
        "%16,%17,%18,%19,%20,%21,%22,%23,%24,%25,%26,%27,%28,%29,%30,%31}, [%32];" \
        : "=r"((r)[0]),"=r"((r)[1]),"=r"((r)[2]),"=r"((r)[3]),"=r"((r)[4]),"=r"((r)[5]), \
          "=r"((r)[6]),"=r"((r)[7]),"=r"((r)[8]),"=r"((r)[9]),"=r"((r)[10]),"=r"((r)[11]), \
          "=r"((r)[12]),"=r"((r)[13]),"=r"((r)[14]),"=r"((r)[15]),"=r"((r)[16]),"=r"((r)[17]), \
          "=r"((r)[18]),"=r"((r)[19]),"=r"((r)[20]),"=r"((r)[21]),"=r"((r)[22]),"=r"((r)[23]), \
          "=r"((r)[24]),"=r"((r)[25]),"=r"((r)[26]),"=r"((r)[27]),"=r"((r)[28]),"=r"((r)[29]), \
          "=r"((r)[30]),"=r"((r)[31]) : "r"(addr))

#define CP_ASYNC16(dst, src) \
    asm volatile("cp.async.cg.shared.global [%0], [%1], 16;" \
                 :: "r"(dst), "l"(src) : "memory")
#define CP_ASYNC16_SZ(dst, src, sz) \
    asm volatile("cp.async.cg.shared.global [%0], [%1], 16, %2;" \
                 :: "r"(dst), "l"(src), "r"(sz) : "memory")
#define CP_COMMIT() asm volatile("cp.async.commit_group;" ::: "memory")
#define CP_WAIT0()  asm volatile("cp.async.wait_group 0;" ::: "memory")
#define CP_WAIT1()  asm volatile("cp.async.wait_group 1;" ::: "memory")
#define CP_WAIT2()  asm volatile("cp.async.wait_group 2;" ::: "memory")

// 64-bit SMEM descriptor: SW128, version=1 (Blackwell), SBO=64, LBO=1
__device__ __forceinline__ uint64_t make_desc(uint32_t addr) {
    const uint64_t base = (uint64_t(2) << 61) | (uint64_t(1) << 46)
                        | (uint64_t(64) << 32) | (uint64_t(1) << 16);
    return base | ((uint64_t)(addr >> 4) & 0x3FFF);
}

// tcgen05 SS tf32 MMA: D[tmem] (+)= A(desc) * B(desc)^T
__device__ __forceinline__ void mma_tf32_ss(uint32_t d_tmem, uint64_t a_desc,
                                            uint64_t b_desc, uint32_t idesc, bool acc) {
    uint32_t en = acc ? 1u : 0u;
    asm volatile(
        "{\n\t.reg .pred p;\n\t"
        "setp.ne.u32 p, %5, 0;\n\t"
        "tcgen05.mma.cta_group::1.kind::tf32 [%0], %1, %2, %3, {%4, %4, %4, %4}, p;\n\t}"
        :: "r"(d_tmem), "l"(a_desc), "l"(b_desc), "r"(idesc), "r"(0u), "r"(en)
        : "memory");
}
#endif // USE_TCGEN05

// ---------------------------------------------------------------------------
// GEMM. C[M,N] = epi(A[M,K] @ Bt[N,K]^T). 256 threads/CTA.
// Template: NT = N-tile (128 or 256), NS = pipeline stages (3 or 4).
// EPI 0: C = acc + bias[n]
// EPI 1: C = tanh(acc + bias[n])
// EPI 3: main fused — scores partial: spart[slot, gm, 0..3],
//        slot = blockIdx.x*(NT/128) + col_half
// ---------------------------------------------------------------------------
template <int EPI, int NT, int NS>
__global__ void __launch_bounds__(256)
k_tcgemm(const float* __restrict__ A, long long sAz, int lda,
         const float* __restrict__ Bt, long long sBz,
         float* __restrict__ C, long long sCz, int ldc,
         const float* __restrict__ bias, long long sbz,
         const float* __restrict__ xq, const float* __restrict__ Wa,
         float* __restrict__ spart,
         int M, int Ntot, int K)
{
    extern __shared__ __align__(1024) char smem[];
    const int tid  = threadIdx.x;
    const int m0   = blockIdx.y * 128;
    const int n0   = blockIdx.x * NT;
    const int z    = blockIdx.z;
    constexpr int HALVES = NT / 128;

    A    += (size_t)z * sAz;
    Bt   += (size_t)z * sBz;
    if (C)    C    += (size_t)z * sCz;
    if (bias) bias += (size_t)z * sbz;

#if USE_TCGEN05
    const int wid  = tid >> 5;
    const int lane = tid & 31;

    constexpr uint32_t STAGE = 16384u + (uint32_t)NT * 128u;  // A 16KB + B NT*128B
    constexpr uint32_t CTRL  = (uint32_t)NS * STAGE;
    constexpr uint32_t IDESC = (1u<<4) | (2u<<7) | (2u<<10)
                             | ((uint32_t)(NT/8) << 17) | (8u << 24);

    const uint32_t smem_b = smem_u32(smem);
    uint32_t mb[NS];
#pragma unroll
    for (int i = 0; i < NS; i++) mb[i] = smem_b + CTRL + 8 + 8 * i;

    if (tid == 0) {
#pragma unroll
        for (int i = 0; i < NS; i++) MBARRIER_INIT(mb[i], 1);
    }
    if (wid == 0) {
        TCGEN05_ALLOC(smem_b + CTRL, NT);
        TCGEN05_RELINQ();
    }
    __syncthreads();

    uint32_t tmem;
    asm volatile("ld.shared.b32 %0, [%1];" : "=r"(tmem) : "r"(smem_b + CTRL));

    const int NK = K >> 5;

    // ---- stage loader: A 128 rows, B NT rows x 32 k-floats (cp.async, SW128) ----
    auto load_stage = [&](int it2, int dbuf) {
        const uint32_t abase = smem_b + (uint32_t)dbuf * STAGE;
        const uint32_t bbase = abase + 16384u;
        const float* Ab = A + (size_t)m0 * lda + (it2 << 5);
        const float* Bb = Bt + (it2 << 5);
#pragma unroll
        for (int i = 0; i < 4; i++) {            // A: 1024 16B-chunks
            int c = tid + (i << 8);
            int row = c >> 3, quad = c & 7;
            uint32_t off = (uint32_t)(row << 7) + (quad << 4);
            off ^= (off >> 3) & 0x70;
            CP_ASYNC16(abase + off, Ab + (size_t)row * lda + (quad << 2));
        }
#pragma unroll
        for (int i = 0; i < NT / 32; i++) {      // B: NT*8 chunks
            int c = tid + (i << 8);
            int row = c >> 3, quad = c & 7;
            int n = n0 + row;
            uint32_t off = (uint32_t)(row << 7) + (quad << 4);
            off ^= (off >> 3) & 0x70;
            const float* src = (n < Ntot) ? (Bb + (size_t)n * K + (quad << 2)) : Bb;
            int sz = (n < Ntot) ? 16 : 0;
            CP_ASYNC16_SZ(bbase + off, src, sz);
        }
    };

    // prologue: NS-1 stages in flight
#pragma unroll
    for (int s = 0; s < NS - 1; s++) { load_stage(s, s); CP_COMMIT(); }

    int mph[NS];
#pragma unroll
    for (int i = 0; i < NS; i++) mph[i] = 0;

    for (int it = 0; it < NK; it++) {
        const int buf = it % NS;
        int pend = NK - 1 - it;
        if (pend > NS - 2) pend = NS - 2;
        if (pend <= 0) CP_WAIT0();
        else if (pend == 1) CP_WAIT1();
        else CP_WAIT2();
        asm volatile("fence.proxy.async.shared::cta;" ::: "memory");
        __syncthreads();

        if (wid == 0 && elect_one()) {
            uint64_t ad = make_desc(smem_b + (uint32_t)buf * STAGE);
            uint64_t bd = make_desc(smem_b + (uint32_t)buf * STAGE + 16384u);
#pragma unroll
            for (int k = 0; k < 4; k++)   // 4 x (K=8) steps = K32, +2 desc units / 32B
                mma_tf32_ss(tmem, ad + 2 * k, bd + 2 * k, IDESC,
                            (it > 0) || (k > 0));
            TCGEN05_COMMIT(mb[buf]);
        }

        if (it + NS - 1 < NK) {
            if (it >= 1) {
                const int j = (it - 1) % NS;  // buffer (it+NS-1)%NS last used by MMA(it-1)
                MBARRIER_WAIT_PARITY(mb[j], mph[j]);
                mph[j] ^= 1;
            }
            load_stage(it + NS - 1, (it + NS - 1) % NS);
            CP_COMMIT();
        }
    }

    // last commit covers ALL previously issued MMAs (in-order completion)
    const int lj = (NK - 1) % NS;
    MBARRIER_WAIT_PARITY(mb[lj], mph[lj]);
    TCGEN05_FENCE_AFTER();

    // ---- epilogue ----
    uint32_t d[32];

    if (EPI == 3) {
        // 4*HALVES warps: warp w -> rows subpart (w&3), col-half (w>>2)
        if (wid < 4 * HALVES) {
            const int half = wid >> 2;
            const int gm = m0 + (wid & 3) * 32 + lane;
            const int bb = gm / S_;
            const float* xqrow = xq + (size_t)bb * DA_;
            const float4* Wa4 = reinterpret_cast<const float4*>(Wa);
            float s0 = 0.f, s1 = 0.f, s2 = 0.f, s3 = 0.f;
#pragma unroll
            for (int c = 0; c < 4; c++) {
                TCGEN05_LD_X32(d, tmem + half * 128 + c * 32);
                TCGEN05_WAIT_LD();
                const int nb = n0 + half * 128 + c * 32;
#pragma unroll
                for (int j = 0; j < 32; j++) {
                    int n = nb + j;
                    if (n < Ntot) {
                        float acc = __uint_as_float(d[j]);
                        float xv = tanhf(acc + __ldg(bias + n));
                        float xa = tanhf(xv * __ldg(xqrow + n));
                        float4 w = __ldg(Wa4 + n);
                        s0 = fmaf(xa, w.x, s0);
                        s1 = fmaf(xa, w.y, s1);
                        s2 = fmaf(xa, w.z, s2);
                        s3 = fmaf(xa, w.w, s3);
                    }
                }
            }
            float4 sv = make_float4(s0, s1, s2, s3);
            int slot = blockIdx.x * HALVES + half;
            reinterpret_cast<float4*>(spart)[(size_t)slot * M_MAIN + gm] = sv;
        }
    } else {
        // 8 warps: warp w -> rows subpart (w&3), col chunk (w>>2) of NT/2
        const int gm = m0 + (wid & 3) * 32 + lane;
        const int ch = (wid >> 2) * (NT / 2);
        float* Crow = C + (size_t)gm * ldc;
#pragma unroll
        for (int c = 0; c < NT / 64; c++) {
            TCGEN05_LD_X32(d, tmem + ch + c * 32);
            TCGEN05_WAIT_LD();
            const int nb = n0 + ch + c * 32;
#pragma unroll
            for (int jv = 0; jv < 8; jv++) {
                int n = nb + jv * 4;
                if (n < Ntot) {
                    float4 o;
                    float v0 = __uint_as_float(d[jv * 4 + 0]) + __ldg(bias + n + 0);
                    float v1 = __uint_as_float(d[jv * 4 + 1]) + __ldg(bias + n + 1);
                    float v2 = __uint_as_float(d[jv * 4 + 2]) + __ldg(bias + n + 2);
                    float v3 = __uint_as_float(d[jv * 4 + 3]) + __ldg(bias + n + 3);
                    if (EPI == 1) {
                        o.x = tanhf(v0); o.y = tanhf(v1); o.z = tanhf(v2); o.w = tanhf(v3);
                    } else {
                        o.x = v0; o.y = v1; o.z = v2; o.w = v3;
                    }
                    *reinterpret_cast<float4*>(Crow + n) = o;
                }
            }
        }
    }

    __syncthreads();
    if (tid == 0) {
#pragma unroll
        for (int i = 0; i < NS; i++)
            asm volatile("mbarrier.inval.shared.b64 [%0];" :: "r"(mb[i]) : "memory");
    }
    __syncthreads();
    if (wid == 0)
        TCGEN05_DEALLOC(tmem, NT);

#else  // ------------------- fp32 FFMA fallback (compute_103 PTX) -----------
    float* As = reinterpret_cast<float*>(smem);            // [16][64]
    float* Bs = reinterpret_cast<float*>(smem + 4096);     // [16][128]
    float* Cs = reinterpret_cast<float*>(smem + 16384);    // [128][128] (EPI3)
    const int tx = tid & 15;
    const int ty = (tid >> 4) & 7;
    const bool active = tid < 128;

    for (int nh = 0; nh < HALVES; nh++) {
        const int nb0 = n0 + nh * 128;
        for (int mh = 0; mh < 2; mh++) {
            float acc[8][8];
#pragma unroll
            for (int i = 0; i < 8; i++)
#pragma unroll
                for (int j = 0; j < 8; j++) acc[i][j] = 0.f;

            const int mbase = m0 + mh * 64;
            for (int kt = 0; kt < K; kt += 16) {
                if (active) {
#pragma unroll
                    for (int r = 0; r < 2; r++) {
                        int f = tid + r * 128;
                        int row = f >> 2, kq = (f & 3) * 4;
                        float4 v = *reinterpret_cast<const float4*>(
                            &A[(size_t)(mbase + row) * lda + kt + kq]);
                        As[(kq + 0) * 64 + row] = v.x;
                        As[(kq + 1) * 64 + row] = v.y;
                        As[(kq + 2) * 64 + row] = v.z;
                        As[(kq + 3) * 64 + row] = v.w;
                    }
#pragma unroll
                    for (int r = 0; r < 4; r++) {
                        int f = tid + r * 128;
                        int row = f >> 5, cq = (f & 31) * 4;
#pragma unroll
                        for (int q = 0; q < 4; q++) {
                            int n = nb0 + cq + q;
                            Bs[row * 128 + cq + q] =
                                (n < Ntot) ? Bt[(size_t)n * K + kt + row] : 0.f;
                        }
                    }
                }
                __syncthreads();
                if (active) {
#pragma unroll
                    for (int kk = 0; kk < 16; kk++) {
                        float a[8], b[8];
#pragma unroll
                        for (int i = 0; i < 8; i++) a[i] = As[kk * 64 + ty * 8 + i];
#pragma unroll
                        for (int j = 0; j < 8; j++) b[j] = Bs[kk * 128 + tx * 8 + j];
#pragma unroll
                        for (int i = 0; i < 8; i++)
#pragma unroll
                            for (int j = 0; j < 8; j++)
                                acc[i][j] = fmaf(a[i], b[j], acc[i][j]);
                    }
                }
                __syncthreads();
            }

            if (active) {
                if (EPI == 3) {
#pragma unroll
                    for (int i = 0; i < 8; i++) {
                        int grow = mh * 64 + ty * 8 + i;
                        int gm = m0 + grow;
                        int bb = gm / S_;
#pragma unroll
                        for (int j = 0; j < 8; j++) {
                            int n = nb0 + tx * 8 + j;
                            float xa = 0.f;
                            if (n < Ntot) {
                                float xv = tanhf(acc[i][j] + bias[n]);
                                xa = tanhf(xv * xq[(size_t)bb * DA_ + n]);
                            }
                            Cs[grow * 128 + tx * 8 + j] = xa;
                        }
                    }
                } else {
#pragma unroll
                    for (int i = 0; i < 8; i++) {
                        int gm = m0 + mh * 64 + ty * 8 + i;
                        float* Crow = C + (size_t)gm * ldc;
#pragma unroll
                        for (int j = 0; j < 8; j++) {
                            int n = nb0 + tx * 8 + j;
                            if (n < Ntot) {
                                float v = acc[i][j] + (bias ? bias[n] : 0.f);
                                Crow[n] = (EPI == 1) ? tanhf(v) : v;
                            }
                        }
                    }
                }
            }
            __syncthreads();
        }

        if (EPI == 3 && active) {
            int row = tid;
            int gm = m0 + row;
            float s0 = 0.f, s1 = 0.f, s2 = 0.f, s3 = 0.f;
            for (int j = 0; j < 128; j++) {
                int n = nb0 + j;
                if (n < Ntot) {
                    float xa = Cs[row * 128 + j];
                    s0 = fmaf(xa, Wa[n * 4 + 0], s0);
                    s1 = fmaf(xa, Wa[n * 4 + 1], s1);
                    s2 = fmaf(xa, Wa[n * 4 + 2], s2);
                    s3 = fmaf(xa, Wa[n * 4 + 3], s3);
                }
            }
            int slot = blockIdx.x * HALVES + nh;
            reinterpret_cast<float4*>(spart)[(size_t)slot * M_MAIN + gm] =
                make_float4(s0, s1, s2, s3);
        }
        __syncthreads();
    }
#endif
}

// ---------------------------------------------------------------------------
// transpose input_v [B, DV, S] -> At [B*S, DV] (tf32-rounded)
// ---------------------------------------------------------------------------
__global__ void k_transpose(const float* __restrict__ v, float* __restrict__ At)
{
    __shared__ float t[32][33];
    int b  = blockIdx.z;
    int s0 = blockIdx.x * 32;
    int c0 = blockIdx.y * 32;
    int tx = threadIdx.x, ty = threadIdx.y;

    int s = s0 + tx, c = c0 + ty;
    if (s < S_)
        t[ty][tx] = v[((size_t)b * DV_ + c) * S_ + s];
    __syncthreads();

    s = s0 + ty; c = c0 + tx;
    if (s < S_)
        At[((size_t)b * S_ + s) * DV_ + c] = to_tf32(t[tx][ty]);
}

// ---------------------------------------------------------------------------
// weight transpose [R, Cn] -> [Cn, R] (tf32-rounded), batched over z
// ---------------------------------------------------------------------------
__global__ void k_wtrans(const float* __restrict__ W, float* __restrict__ Wt,
                         int R, int Cn)
{
    __shared__ float t[32][33];
    size_t zo = (size_t)blockIdx.z * R * Cn;
    int c0 = blockIdx.x * 32;
    int r0 = blockIdx.y * 32;
    int tx = threadIdx.x, ty = threadIdx.y;

    int r = r0 + ty, c = c0 + tx;
    if (r < R && c < Cn)
        t[ty][tx] = W[zo + (size_t)r * Cn + c];
    __syncthreads();

    c = c0 + ty; r = r0 + tx;
    if (c < Cn && r < R)
        Wt[zo + (size_t)c * R + r] = to_tf32(t[tx][ty]);
}

// rounded copy of q
__global__ void k_qround(const float* __restrict__ q, float* __restrict__ qr)
{
    int i = blockIdx.x * 256 + threadIdx.x;
    if (i < B_ * DQ_)
        qr[i] = to_tf32(q[i]);
}

// scores[row, g] = ba[g] + sum_slot spart[slot, row, g]
__global__ void k_scores_reduce(const float* __restrict__ spart,
                                const float* __restrict__ ba,
                                float* __restrict__ scores, int nslot)
{
    int row = blockIdx.x * 256 + threadIdx.x;
    if (row >= M_MAIN) return;
    float s0 = __ldg(ba + 0), s1 = __ldg(ba + 1), s2 = __ldg(ba + 2), s3 = __ldg(ba + 3);
    const float4* sp = reinterpret_cast<const float4*>(spart);
    for (int nb = 0; nb < nslot; nb++) {
        float4 p = sp[(size_t)nb * M_MAIN + row];
        s0 += p.x; s1 += p.y; s2 += p.z; s3 += p.w;
    }
    reinterpret_cast<float4*>(scores)[row] = make_float4(s0, s1, s2, s3);
}

// softmax over spatial axis, block per (b, g)
__global__ void k_softmax(const float* __restrict__ scores, float* __restrict__ att)
{
    int b = blockIdx.x >> 2;
    int g = blockIdx.x & 3;
    int tid = threadIdx.x;
    __shared__ float red[256];

    const float* sp = scores + (size_t)b * S_ * G_ + g;
    float v = (tid < S_) ? sp[tid * G_] : -1e30f;

    red[tid] = v;
    __syncthreads();
#pragma unroll
    for (int o = 128; o; o >>= 1) {
        if (tid < o) red[tid] = fmaxf(red[tid], red[tid + o]);
        __syncthreads();
    }
    float mx = red[0];
    __syncthreads();

    float e = (tid < S_) ? expf(v - mx) : 0.f;
    red[tid] = e;
    __syncthreads();
#pragma unroll
    for (int o = 128; o; o >>= 1) {
        if (tid < o) red[tid] += red[tid + o];
        __syncthreads();
    }
    float inv = 1.f / red[0];

    if (tid < S_)
        att[(size_t)b * S_ * G_ + tid * G_ + g] = e * inv;
}

// v_att[b,g,c] = sum_s att[b,s,g] * v[b,c,s]  (tf32-rounded output)
__global__ void k_pool(const float* __restrict__ v, const float* __restrict__ att,
                       float* __restrict__ vatt)
{
    __shared__ float satt[G_][S_];
    int tid = threadIdx.x;
    int b     = blockIdx.x / (DV_ / 8);
    int cBase = (blockIdx.x % (DV_ / 8)) * 8;

    const float* ap = att + (size_t)b * S_ * G_;
    for (int i = tid; i < S_ * G_; i += 256)
        satt[i & 3][i >> 2] = ap[i];
    __syncthreads();

    int warp = tid >> 5, lane = tid & 31;
    int c = cBase + warp;
    const float* vp = v + ((size_t)b * DV_ + c) * S_;

    float a0 = 0.f, a1 = 0.f, a2 = 0.f, a3 = 0.f;
    for (int s = lane; s < S_; s += 32) {
        float x = vp[s];
        a0 = fmaf(x, satt[0][s], a0);
        a1 = fmaf(x, satt[1][s], a1);
        a2 = fmaf(x, satt[2][s], a2);
        a3 = fmaf(x, satt[3][s], a3);
    }
#pragma unroll
    for (int o = 16; o; o >>= 1) {
        a0 += __shfl_xor_sync(0xffffffff, a0, o);
        a1 += __shfl_xor_sync(0xffffffff, a1, o);
        a2 += __shfl_xor_sync(0xffffffff, a2, o);
        a3 += __shfl_xor_sync(0xffffffff, a3, o);
    }
    if (lane == 0) {
        vatt[((size_t)b * G_ + 0) * DV_ + c] = to_tf32(a0);
        vatt[((size_t)b * G_ + 1) * DV_ + c] = to_tf32(a1);
        vatt[((size_t)b * G_ + 2) * DV_ + c] = to_tf32(a2);
        vatt[((size_t)b * G_ + 3) * DV_ + c] = to_tf32(a3);
    }
}

// x_fused = tf32(tanh(xv * xqf))
__global__ void k_ewfuse(const float* __restrict__ xv, const float* __restrict__ xqf,
                         float* __restrict__ out)
{
    int i = blockIdx.x * 256 + threadIdx.x;
    if (i < B_ * DH_)
        out[i] = to_tf32(tanhf(xv[i] * xqf[i]));
}

// ---------------------------------------------------------------------------
// host launcher
// ---------------------------------------------------------------------------
extern "C" void kernel_launch(void* const* d_in, const int* in_sizes, int n_in,
                              void* d_out, int out_size)
{
    const float* input_v = (const float*)d_in[0];
    const float* x_q_vec = (const float*)d_in[1];
    const float* Wv_att  = (const float*)d_in[2];
    const float* bv_att  = (const float*)d_in[3];
    const float* Wq_att  = (const float*)d_in[4];
    const float* bq_att  = (const float*)d_in[5];
    const float* Wa      = (const float*)d_in[6];
    const float* ba      = (const float*)d_in[7];
    const float* Wf      = (const float*)d_in[8];
    const float* bf      = (const float*)d_in[9];
    const float* Wqf     = (const float*)d_in[10];
    const float* bqf     = (const float*)d_in[11];
    const float* Wc      = (const float*)d_in[12];
    const float* bc      = (const float*)d_in[13];
    float* out = (float*)d_out;

    float *At, *Btv, *Btqa, *Btqf, *Btc, *Btf, *qr, *xq_att, *spart, *scores,
          *att, *vatt, *xv, *xqf, *xfused;
    cudaGetSymbolAddress((void**)&At,     g_At);
    cudaGetSymbolAddress((void**)&Btv,    g_Bt_v);
    cudaGetSymbolAddress((void**)&Btqa,   g_Bt_qatt);
    cudaGetSymbolAddress((void**)&Btqf,   g_Bt_qf);
    cudaGetSymbolAddress((void**)&Btc,    g_Bt_c);
    cudaGetSymbolAddress((void**)&Btf,    g_Bt_f);
    cudaGetSymbolAddress((void**)&qr,     g_qr);
    cudaGetSymbolAddress((void**)&xq_att, g_xq_att);
    cudaGetSymbolAddress((void**)&spart,  g_spart);
    cudaGetSymbolAddress((void**)&scores, g_scores);
    cudaGetSymbolAddress((void**)&att,    g_att);
    cudaGetSymbolAddress((void**)&vatt,   g_vatt);
    cudaGetSymbolAddress((void**)&xv,     g_xv);
    cudaGetSymbolAddress((void**)&xqf,    g_xqf);
    cudaGetSymbolAddress((void**)&xfused, g_xfused);

    const int SMEM128 = 3 * (16384 + 128 * 128) + 64;   // 98368
    const int SMEM256 = 4 * (16384 + 256 * 128) + 64;   // 196672
    cudaFuncSetAttribute(k_tcgemm<0,128,3>, cudaFuncAttributeMaxDynamicSharedMemorySize, SMEM128);
    cudaFuncSetAttribute(k_tcgemm<1,128,3>, cudaFuncAttributeMaxDynamicSharedMemorySize, SMEM128);
    cudaFuncSetAttribute(k_tcgemm<3,256,4>, cudaFuncAttributeMaxDynamicSharedMemorySize, SMEM256);

    dim3 t32(32, 32);

    /*0*/ k_transpose<<<dim3(7, DV_ / 32, B_), t32>>>(input_v, At);
    /*1*/ k_wtrans<<<dim3((DA_ + 31) / 32, DV_ / 32, 1), t32>>>(Wv_att, Btv, DV_, DA_);
    /*2*/ k_wtrans<<<dim3((DA_ + 31) / 32, DQ_ / 32, 1), t32>>>(Wq_att, Btqa, DQ_, DA_);
    /*3*/ k_qround<<<(B_ * DQ_ + 255) / 256, 256>>>(x_q_vec, qr);

    // xq_att = tanh(q @ Wq_att + bq_att)   [128, 1200]
    /*4*/ k_tcgemm<1,128,3><<<dim3(10, 1, 1), 256, SMEM128>>>(
        qr, 0, DQ_, Btqa, 0, xq_att, 0, DA_, bq_att, 0,
        nullptr, nullptr, nullptr, B_, DA_, DQ_);

    // MAIN fused GEMM (x_att never materialized): N-tile 256, 4-stage pipe
    /*5*/ k_tcgemm<3,256,4><<<dim3(5, M_MAIN / 128, 1), 256, SMEM256>>>(
        At, 0, DV_, Btv, 0, nullptr, 0, 0, bv_att, 0,
        xq_att, Wa, spart, M_MAIN, DA_, DV_);

    // remaining weight transposes (independent of main GEMM)
    /*6*/ k_wtrans<<<dim3(DH_ / 32, DQ_ / 32, 1), t32>>>(Wqf, Btqf, DQ_, DH_);
    /*7*/ k_wtrans<<<dim3((NANS_ + 31) / 32, DH_ / 32, 1), t32>>>(Wc, Btc, DH_, NANS_);
    /*8*/ k_wtrans<<<dim3(DHG_ / 32, DV_ / 32, G_), t32>>>(Wf, Btf, DV_, DHG_);

    // reduce score partials + bias (10 slots = 5 blocks x 2 halves)
    /*9*/ k_scores_reduce<<<(M_MAIN + 255) / 256, 256>>>(spart, ba, scores, NSLOT_MAIN);

    // softmax over spatial
    /*10*/ k_softmax<<<B_ * G_, 256>>>(scores, att);

    // attention pooling
    /*11*/ k_pool<<<B_ * (DV_ / 8), 256>>>(input_v, att, vatt);

    // glimpse fusion (batched over g)
    /*12*/ k_tcgemm<1,128,3><<<dim3(DHG_ / 128, 1, G_), 256, SMEM128>>>(
        vatt, DV_, G_ * DV_, Btf, (long long)DHG_ * DV_,
        xv, DHG_, DH_, bf, DHG_,
        nullptr, nullptr, nullptr, B_, DHG_, DV_);

    // xqf = tanh(q @ Wqf + bqf)   [128, 2048]
    /*13*/ k_tcgemm<1,128,3><<<dim3(DH_ / 128, 1, 1), 256, SMEM128>>>(
        qr, 0, DQ_, Btqf, 0, xqf, 0, DH_, bqf, 0,
        nullptr, nullptr, nullptr, B_, DH_, DQ_);

    // x = tf32(tanh(xv * xqf))
    /*14*/ k_ewfuse<<<(B_ * DH_ + 255) / 256, 256>>>(xv, xqf, xfused);

    // classifier: out = x @ Wc + bc   [128, 3000]
    /*15*/ k_tcgemm<0,128,3><<<dim3((NANS_ + 127) / 128, 1, 1), 256, SMEM128>>>(
        xfused, 0, DH_, Btc, 0, out, 0, NANS_, bc, 0,
        nullptr, nullptr, nullptr, B_, NANS_, DH_);
}

// round 13
// speedup vs baseline: 1.0258x; 1.0258x over previous
#include <cuda_runtime.h>
#include <cstdint>

// ---------------------------------------------------------------------------
// Arch feature gate: tcgen05 only exists on the sm_103a/sm_100a targets.
// The harness also assembles a plain compute_103 PTX — that pass gets the
// fp32 fallback bodies below (same kernel symbols, same launcher).
// ---------------------------------------------------------------------------
#if defined(__CUDA_ARCH__) && defined(__CUDA_ARCH_HAS_FEATURE__)
#  if __CUDA_ARCH_HAS_FEATURE__(SM103_ALL) || __CUDA_ARCH_HAS_FEATURE__(SM100_ALL)
#    define USE_TCGEN05 1
#  endif
#endif
#ifndef USE_TCGEN05
#  define USE_TCGEN05 0
#endif

// ---------------------------------------------------------------------------
// Problem constants
// ---------------------------------------------------------------------------
#define B_    128
#define DV_   2048
#define S_    196
#define DQ_   2048
#define DA_   1200
#define G_    4
#define DH_   2048
#define DHG_  512
#define NANS_ 3000
#define M_MAIN (B_ * S_)       // 25088
#define NSLOT_MAIN 10          // 10 N-blocks of 128

// ---------------------------------------------------------------------------
// Static scratch (no cudaMalloc allowed)
// ---------------------------------------------------------------------------
__device__ float g_At[(size_t)M_MAIN * DV_];        // [B*S, DV] tf32-rounded
__device__ float g_Bt_v[(size_t)DA_ * DV_];         // Wv_att^T   [1200,2048]
__device__ float g_Bt_qatt[(size_t)DA_ * DQ_];      // Wq_att^T   [1200,2048]
__device__ float g_Bt_qf[(size_t)DH_ * DQ_];        // Wqf^T      [2048,2048]
__device__ float g_Bt_c[(size_t)NANS_ * DH_];       // Wc^T       [3000,2048]
__device__ float g_Bt_f[(size_t)G_ * DHG_ * DV_];   // Wf^T per g [4,512,2048]
__device__ float g_qr[B_ * DQ_];                    // tf32-rounded q
__device__ float g_xq_att[B_ * DA_];
__device__ float g_spart[(size_t)NSLOT_MAIN * M_MAIN * G_]; // score partials
__device__ float g_att[M_MAIN * G_];
__device__ float g_vatt[B_ * G_ * DV_];
__device__ float g_xv[B_ * DH_];
__device__ float g_xqf[B_ * DH_];
__device__ float g_xfused[B_ * DH_];

// ---------------------------------------------------------------------------
// Common helpers
// ---------------------------------------------------------------------------
__device__ __forceinline__ float to_tf32(float x) {
    float r;
    asm("cvt.rna.tf32.f32 %0, %1;" : "=f"(r) : "f"(x));
    return r;
}

#if USE_TCGEN05
// ---------------------------------------------------------------------------
// PTX helpers (sm_103a only)
// ---------------------------------------------------------------------------
__device__ __forceinline__ uint32_t smem_u32(const void* p) {
    uint32_t a;
    asm("{ .reg .u64 t; cvta.to.shared.u64 t, %1; cvt.u32.u64 %0, t; }"
        : "=r"(a) : "l"(p));
    return a;
}
__device__ __forceinline__ uint32_t elect_one() {
    uint32_t pred;
    asm volatile("{ .reg .pred p; elect.sync _|p, 0xFFFFFFFF; selp.b32 %0, 1, 0, p; }"
                 : "=r"(pred));
    return pred;
}

#define MBARRIER_INIT(addr, cnt) \
    asm volatile("mbarrier.init.shared.b64 [%0], %1;" :: "r"(addr), "r"(cnt) : "memory")

#define MBARRIER_WAIT_PARITY(addr, par) do {                                        \
    uint32_t _m = (addr), _p = (par), _d;                                           \
    asm volatile("{ .reg .pred p; mbarrier.try_wait.parity.acquire.cta.shared::cta.b64 p, [%1], %2;" \
                 " selp.b32 %0, 1, 0, p; }" : "=r"(_d) : "r"(_m), "r"(_p) : "memory"); \
    if (!_d) {                                                                      \
        asm volatile("{ .reg .pred P1;\n"                                           \
            "W_%=: mbarrier.try_wait.parity.acquire.cta.shared::cta.b64 P1, [%0], %1, 0x989680;\n" \
            "@P1 bra.uni D_%=;\n bra.uni W_%=;\n D_%=: }"                           \
            :: "r"(_m), "r"(_p) : "memory");                                        \
    }                                                                               \
} while (0)

#define TCGEN05_ALLOC(smem_addr, n) \
    asm volatile("tcgen05.alloc.cta_group::1.sync.aligned.shared::cta.b32 [%0], %1;" \
                 :: "r"(smem_addr), "r"((uint32_t)(n)) : "memory")
#define TCGEN05_RELINQ() \
    asm volatile("tcgen05.relinquish_alloc_permit.cta_group::1.sync.aligned;")
#define TCGEN05_DEALLOC(tmem, n) \
    asm volatile("tcgen05.dealloc.cta_group::1.sync.aligned.b32 %0, %1;" :: "r"(tmem), "r"((uint32_t)(n)))
#define TCGEN05_COMMIT(mbar) \
    asm volatile("tcgen05.commit.cta_group::1.mbarrier::arrive::one.shared::cluster.b64 [%0];" \
                 :: "r"(mbar) : "memory")
#define TCGEN05_WAIT_LD() asm volatile("tcgen05.wait::ld.sync.aligned;" ::: "memory")
#define TCGEN05_FENCE_AFTER() asm volatile("tcgen05.fence::after_thread_sync;" ::: "memory")

#define TCGEN05_LD_X32(r, addr) \
    asm volatile("tcgen05.ld.sync.aligned.32x32b.x32.b32 " \
        "{%0,%1,%2,%3,%4,%5,%6,%7,%8,%9,%10,%11,%12,%13,%14,%15," \
        "%16,%17,%18,%19,%20,%21,%22,%23,%24,%25,%26,%27,%28,%29,%30,%31}, [%32];" \
        : "=r"((r)[0]),"=r"((r)[1]),"=r"((r)[2]),"=r"((r)[3]),"=r"((r)[4]),"=r"((r)[5]), \
          "=r"((r)[6]),"=r"((r)[7]),"=r"((r)[8]),"=r"((r)[9]),"=r"((r)[10]),"=r"((r)[11]), \
          "=r"((r)[12]),"=r"((r)[13]),"=r"((r)[14]),"=r"((r)[15]),"=r"((r)[16]),"=r"((r)[17]), \
          "=r"((r)[18]),"=r"((r)[19]),"=r"((r)[20]),"=r"((r)[21]),"=r"((r)[22]),"=r"((r)[23]), \
          "=r"((r)[24]),"=r"((r)[25]),"=r"((r)[26]),"=r"((r)[27]),"=r"((r)[28]),"=r"((r)[29]), \
          "=r"((r)[30]),"=r"((r)[31]) : "r"(addr))

#define CP_ASYNC16(dst, src) \
    asm volatile("cp.async.cg.shared.global [%0], [%1], 16;" \
                 :: "r"(dst), "l"(src) : "memory")
#define CP_ASYNC16_SZ(dst, src, sz) \
    asm volatile("cp.async.cg.shared.global [%0], [%1], 16, %2;" \
                 :: "r"(dst), "l"(src), "r"(sz) : "memory")
#define CP_COMMIT() asm volatile("cp.async.commit_group;" ::: "memory")
#define CP_WAIT0()  asm volatile("cp.async.wait_group 0;" ::: "memory")
#define CP_WAIT1()  asm volatile("cp.async.wait_group 1;" ::: "memory")

// 64-bit SMEM descriptor: SW128, version=1 (Blackwell), SBO=64, LBO=1
__device__ __forceinline__ uint64_t make_desc(uint32_t addr) {
    const uint64_t base = (uint64_t(2) << 61) | (uint64_t(1) << 46)
                        | (uint64_t(64) << 32) | (uint64_t(1) << 16);
    return base | ((uint64_t)(addr >> 4) & 0x3FFF);
}

// tcgen05 SS tf32 MMA: D[tmem] (+)= A(desc) * B(desc)^T
__device__ __forceinline__ void mma_tf32_ss(uint32_t d_tmem, uint64_t a_desc,
                                            uint64_t b_desc, uint32_t idesc, bool acc) {
    uint32_t en = acc ? 1u : 0u;
    asm volatile(
        "{\n\t.reg .pred p;\n\t"
        "setp.ne.u32 p, %5, 0;\n\t"
        "tcgen05.mma.cta_group::1.kind::tf32 [%0], %1, %2, %3, {%4, %4, %4, %4}, p;\n\t}"
        :: "r"(d_tmem), "l"(a_desc), "l"(b_desc), "r"(idesc), "r"(0u), "r"(en)
        : "memory");
}

// idesc: dtype=F32(1)<<4, atype=TF32(2)<<7, btype=TF32(2)<<10, N>>3<<17, M>>4<<24
#define IDESC_TF32_128x128 ((1u<<4) | (2u<<7) | (2u<<10) | (16u<<17) | (8u<<24))
#endif // USE_TCGEN05

// ---------------------------------------------------------------------------
// GEMM. C[M,N] = epi(A[M,K] @ Bt[N,K]^T). 256 threads/CTA.
// N-tile 128, 3-stage cp.async pipeline (R8-proven config, 2 CTA/SM).
// EPI 0: C = acc + bias[n]
// EPI 1: C = tanh(acc + bias[n])
// EPI 3: main fused — scores partial: spart[blockIdx.x, gm, 0..3]
// Dynamic smem: 98368 bytes.
// ---------------------------------------------------------------------------
template <int EPI>
__global__ void __launch_bounds__(256)
k_tcgemm(const float* __restrict__ A, long long sAz, int lda,
         const float* __restrict__ Bt, long long sBz,
         float* __restrict__ C, long long sCz, int ldc,
         const float* __restrict__ bias, long long sbz,
         const float* __restrict__ xq, const float* __restrict__ Wa,
         float* __restrict__ spart,
         int M, int Ntot, int K)
{
    extern __shared__ __align__(1024) char smem[];
    const int tid  = threadIdx.x;
    const int m0   = blockIdx.y * 128;
    const int n0   = blockIdx.x * 128;
    const int z    = blockIdx.z;

    A    += (size_t)z * sAz;
    Bt   += (size_t)z * sBz;
    if (C)    C    += (size_t)z * sCz;
    if (bias) bias += (size_t)z * sbz;

#if USE_TCGEN05
    const int wid  = tid >> 5;
    const int lane = tid & 31;

    const uint32_t STAGE = 32768u;                // A 16KB + B 16KB
    const uint32_t CTRL  = 3u * STAGE;            // 98304
    const uint32_t smem_b = smem_u32(smem);
    const uint32_t mb[3] = {smem_b + CTRL + 8, smem_b + CTRL + 16, smem_b + CTRL + 24};

    if (tid == 0) {
        MBARRIER_INIT(mb[0], 1);
        MBARRIER_INIT(mb[1], 1);
        MBARRIER_INIT(mb[2], 1);
    }
    if (wid == 0) {
        TCGEN05_ALLOC(smem_b + CTRL, 128);
        TCGEN05_RELINQ();
    }
    __syncthreads();

    uint32_t tmem;
    asm volatile("ld.shared.b32 %0, [%1];" : "=r"(tmem) : "r"(smem_b + CTRL));

    const int NK = K >> 5;

    // ---- stage loader: A 128 rows, B 128 rows x 32 k-floats (cp.async, SW128) ----
    auto load_stage = [&](int it2, int dbuf) {
        const uint32_t abase = smem_b + (uint32_t)dbuf * STAGE;
        const uint32_t bbase = abase + 16384u;
        const float* Ab = A + (size_t)m0 * lda + (it2 << 5);
        const float* Bb = Bt + (it2 << 5);
#pragma unroll
        for (int i = 0; i < 4; i++) {            // A: 1024 16B-chunks
            int c = tid + (i << 8);
            int row = c >> 3, quad = c & 7;
            uint32_t off = (uint32_t)(row << 7) + (quad << 4);
            off ^= (off >> 3) & 0x70;
            CP_ASYNC16(abase + off, Ab + (size_t)row * lda + (quad << 2));
        }
#pragma unroll
        for (int i = 0; i < 4; i++) {            // B: 1024 chunks (zero-pad n>=Ntot)
            int c = tid + (i << 8);
            int row = c >> 3, quad = c & 7;
            int n = n0 + row;
            uint32_t off = (uint32_t)(row << 7) + (quad << 4);
            off ^= (off >> 3) & 0x70;
            const float* src = (n < Ntot) ? (Bb + (size_t)n * K + (quad << 2)) : Bb;
            int sz = (n < Ntot) ? 16 : 0;
            CP_ASYNC16_SZ(bbase + off, src, sz);
        }
    };

    // prologue: stages 0 and 1 in flight
    load_stage(0, 0); CP_COMMIT();
    load_stage(1, 1); CP_COMMIT();

    int mph[3] = {0, 0, 0};

    for (int it = 0; it < NK; it++) {
        const int buf = it % 3;
        if (it < NK - 1) CP_WAIT1(); else CP_WAIT0();   // group(it) complete
        asm volatile("fence.proxy.async.shared::cta;" ::: "memory");
        __syncthreads();

        if (wid == 0 && elect_one()) {
            uint64_t ad = make_desc(smem_b + (uint32_t)buf * STAGE);
            uint64_t bd = make_desc(smem_b + (uint32_t)buf * STAGE + 16384u);
#pragma unroll
            for (int k = 0; k < 4; k++)   // 4 x (K=8) steps = K32, +2 desc units / 32B
                mma_tf32_ss(tmem, ad + 2 * k, bd + 2 * k, IDESC_TF32_128x128,
                            (it > 0) || (k > 0));
            TCGEN05_COMMIT(mb[buf]);
        }

        if (it + 2 < NK) {
            if (it >= 1) {
                const int j = (it - 1) % 3;   // buffer (it+2)%3 last used by MMA(it-1)
                MBARRIER_WAIT_PARITY(mb[j], mph[j]);
                mph[j] ^= 1;
            }
            load_stage(it + 2, (it + 2) % 3);
            CP_COMMIT();
        }
    }

    // last commit covers ALL previously issued MMAs (in-order completion)
    const int lj = (NK - 1) % 3;
    MBARRIER_WAIT_PARITY(mb[lj], mph[lj]);
    TCGEN05_FENCE_AFTER();

    // ---- epilogue ----
    uint32_t d[32];

    if (EPI == 3) {
        // warps 0-3: full 128 cols for their 32 rows
        if (wid < 4) {
            const int gm = m0 + wid * 32 + lane;
            const int bb = gm / S_;
            const float* xqrow = xq + (size_t)bb * DA_;
            const float4* Wa4 = reinterpret_cast<const float4*>(Wa);
            float s0 = 0.f, s1 = 0.f, s2 = 0.f, s3 = 0.f;
#pragma unroll
            for (int c = 0; c < 4; c++) {
                TCGEN05_LD_X32(d, tmem + c * 32);
                TCGEN05_WAIT_LD();
                const int nb = n0 + c * 32;
#pragma unroll
                for (int j = 0; j < 32; j++) {
                    int n = nb + j;
                    if (n < Ntot) {
                        float acc = __uint_as_float(d[j]);
                        float xv = tanhf(acc + __ldg(bias + n));
                        float xa = tanhf(xv * __ldg(xqrow + n));
                        float4 w = __ldg(Wa4 + n);
                        s0 = fmaf(xa, w.x, s0);
                        s1 = fmaf(xa, w.y, s1);
                        s2 = fmaf(xa, w.z, s2);
                        s3 = fmaf(xa, w.w, s3);
                    }
                }
            }
            float4 sv = make_float4(s0, s1, s2, s3);
            reinterpret_cast<float4*>(spart)[(size_t)blockIdx.x * M_MAIN + gm] = sv;
        }
    } else {
        // 8 warps: warp w -> rows subpart (w&3), col-half (w>>2)
        const int gm = m0 + (wid & 3) * 32 + lane;
        const int ch = (wid >> 2) * 64;
        float* Crow = C + (size_t)gm * ldc;
#pragma unroll
        for (int c = 0; c < 2; c++) {
            TCGEN05_LD_X32(d, tmem + ch + c * 32);
            TCGEN05_WAIT_LD();
            const int nb = n0 + ch + c * 32;
#pragma unroll
            for (int jv = 0; jv < 8; jv++) {
                int n = nb + jv * 4;
                if (n < Ntot) {
                    float4 o;
                    float v0 = __uint_as_float(d[jv * 4 + 0]) + __ldg(bias + n + 0);
                    float v1 = __uint_as_float(d[jv * 4 + 1]) + __ldg(bias + n + 1);
                    float v2 = __uint_as_float(d[jv * 4 + 2]) + __ldg(bias + n + 2);
                    float v3 = __uint_as_float(d[jv * 4 + 3]) + __ldg(bias + n + 3);
                    if (EPI == 1) {
                        o.x = tanhf(v0); o.y = tanhf(v1); o.z = tanhf(v2); o.w = tanhf(v3);
                    } else {
                        o.x = v0; o.y = v1; o.z = v2; o.w = v3;
                    }
                    *reinterpret_cast<float4*>(Crow + n) = o;
                }
            }
        }
    }

    __syncthreads();
    if (tid == 0) {
        asm volatile("mbarrier.inval.shared.b64 [%0];" :: "r"(mb[0]) : "memory");
        asm volatile("mbarrier.inval.shared.b64 [%0];" :: "r"(mb[1]) : "memory");
        asm volatile("mbarrier.inval.shared.b64 [%0];" :: "r"(mb[2]) : "memory");
    }
    __syncthreads();
    if (wid == 0)
        TCGEN05_DEALLOC(tmem, 128);

#else  // ------------------- fp32 FFMA fallback (compute_103 PTX) -----------
    float* As = reinterpret_cast<float*>(smem);            // [16][64]
    float* Bs = reinterpret_cast<float*>(smem + 4096);     // [16][128]
    float* Cs = reinterpret_cast<float*>(smem + 16384);    // [128][128] (EPI3)
    const int tx = tid & 15;
    const int ty = (tid >> 4) & 7;
    const bool active = tid < 128;

    for (int mh = 0; mh < 2; mh++) {
        float acc[8][8];
#pragma unroll
        for (int i = 0; i < 8; i++)
#pragma unroll
            for (int j = 0; j < 8; j++) acc[i][j] = 0.f;

        const int mbase = m0 + mh * 64;
        for (int kt = 0; kt < K; kt += 16) {
            if (active) {
#pragma unroll
                for (int r = 0; r < 2; r++) {
                    int f = tid + r * 128;
                    int row = f >> 2, kq = (f & 3) * 4;
                    float4 v = *reinterpret_cast<const float4*>(
                        &A[(size_t)(mbase + row) * lda + kt + kq]);
                    As[(kq + 0) * 64 + row] = v.x;
                    As[(kq + 1) * 64 + row] = v.y;
                    As[(kq + 2) * 64 + row] = v.z;
                    As[(kq + 3) * 64 + row] = v.w;
                }
#pragma unroll
                for (int r = 0; r < 4; r++) {
                    int f = tid + r * 128;
                    int row = f >> 5, cq = (f & 31) * 4;
#pragma unroll
                    for (int q = 0; q < 4; q++) {
                        int n = n0 + cq + q;
                        Bs[row * 128 + cq + q] =
                            (n < Ntot) ? Bt[(size_t)n * K + kt + row] : 0.f;
                    }
                }
            }
            __syncthreads();
            if (active) {
#pragma unroll
                for (int kk = 0; kk < 16; kk++) {
                    float a[8], b[8];
#pragma unroll
                    for (int i = 0; i < 8; i++) a[i] = As[kk * 64 + ty * 8 + i];
#pragma unroll
                    for (int j = 0; j < 8; j++) b[j] = Bs[kk * 128 + tx * 8 + j];
#pragma unroll
                    for (int i = 0; i < 8; i++)
#pragma unroll
                        for (int j = 0; j < 8; j++)
                            acc[i][j] = fmaf(a[i], b[j], acc[i][j]);
                }
            }
            __syncthreads();
        }

        if (active) {
            if (EPI == 3) {
#pragma unroll
                for (int i = 0; i < 8; i++) {
                    int grow = mh * 64 + ty * 8 + i;
                    int gm = m0 + grow;
                    int bb = gm / S_;
#pragma unroll
                    for (int j = 0; j < 8; j++) {
                        int n = n0 + tx * 8 + j;
                        float xa = 0.f;
                        if (n < Ntot) {
                            float xv = tanhf(acc[i][j] + bias[n]);
                            xa = tanhf(xv * xq[(size_t)bb * DA_ + n]);
                        }
                        Cs[grow * 128 + tx * 8 + j] = xa;
                    }
                }
            } else {
#pragma unroll
                for (int i = 0; i < 8; i++) {
                    int gm = m0 + mh * 64 + ty * 8 + i;
                    float* Crow = C + (size_t)gm * ldc;
#pragma unroll
                    for (int j = 0; j < 8; j++) {
                        int n = n0 + tx * 8 + j;
                        if (n < Ntot) {
                            float v = acc[i][j] + (bias ? bias[n] : 0.f);
                            Crow[n] = (EPI == 1) ? tanhf(v) : v;
                        }
                    }
                }
            }
        }
        __syncthreads();
    }

    if (EPI == 3 && active) {
        int row = tid;
        int gm = m0 + row;
        float s0 = 0.f, s1 = 0.f, s2 = 0.f, s3 = 0.f;
        for (int j = 0; j < 128; j++) {
            int n = n0 + j;
            if (n < Ntot) {
                float xa = Cs[row * 128 + j];
                s0 = fmaf(xa, Wa[n * 4 + 0], s0);
                s1 = fmaf(xa, Wa[n * 4 + 1], s1);
                s2 = fmaf(xa, Wa[n * 4 + 2], s2);
                s3 = fmaf(xa, Wa[n * 4 + 3], s3);
            }
        }
        reinterpret_cast<float4*>(spart)[(size_t)blockIdx.x * M_MAIN + gm] =
            make_float4(s0, s1, s2, s3);
    }
#endif
}

// ---------------------------------------------------------------------------
// transpose input_v [B, DV, S] -> At [B*S, DV] (tf32-rounded)
// ---------------------------------------------------------------------------
__global__ void k_transpose(const float* __restrict__ v, float* __restrict__ At)
{
    __shared__ float t[32][33];
    int b  = blockIdx.z;
    int s0 = blockIdx.x * 32;
    int c0 = blockIdx.y * 32;
    int tx = threadIdx.x, ty = threadIdx.y;

    int s = s0 + tx, c = c0 + ty;
    if (s < S_)
        t[ty][tx] = v[((size_t)b * DV_ + c) * S_ + s];
    __syncthreads();

    s = s0 + ty; c = c0 + tx;
    if (s < S_)
        At[((size_t)b * S_ + s) * DV_ + c] = to_tf32(t[tx][ty]);
}

// ---------------------------------------------------------------------------
// Fused prep: all 5 weight transposes (tf32-rounded) + q rounding in ONE
// kernel, dispatched by linear block ranges. 1024 threads (32x32).
// ---------------------------------------------------------------------------
__device__ __forceinline__ void wtrans_tile(float (*t)[33],
                                            const float* __restrict__ W,
                                            float* __restrict__ Wt,
                                            int R, int Cn, int tile)
{
    int cnt = (Cn + 31) / 32;
    int c0 = (tile % cnt) * 32;
    int r0 = (tile / cnt) * 32;
    int tx = threadIdx.x, ty = threadIdx.y;

    int r = r0 + ty, c = c0 + tx;
    if (r < R && c < Cn)
        t[ty][tx] = W[(size_t)r * Cn + c];
    __syncthreads();

    c = c0 + ty; r = r0 + tx;
    if (c < Cn && r < R)
        Wt[(size_t)c * R + r] = to_tf32(t[tx][ty]);
}

#define PREP_NV   (38 * 64)          // Wv_att  [2048,1200]
#define PREP_NQA  (38 * 64)          // Wq_att  [2048,1200]
#define PREP_NQF  (64 * 64)          // Wqf     [2048,2048]
#define PREP_NC   (94 * 64)          // Wc      [2048,3000]
#define PREP_NF   (16 * 64 * G_)     // Wf      [4,2048,512]
#define PREP_NQ   ((B_ * DQ_) / 1024)
#define PREP_BLOCKS (PREP_NV + PREP_NQA + PREP_NQF + PREP_NC + PREP_NF + PREP_NQ)

__global__ void k_prep(const float* __restrict__ Wv,  const float* __restrict__ Wqa,
                       const float* __restrict__ Wqf, const float* __restrict__ Wc,
                       const float* __restrict__ Wf,  const float* __restrict__ q,
                       float* __restrict__ Btv,  float* __restrict__ Btqa,
                       float* __restrict__ Btqf, float* __restrict__ Btc,
                       float* __restrict__ Btf,  float* __restrict__ qr)
{
    __shared__ float t[32][33];
    int bid = blockIdx.x;

    if (bid < PREP_NV)  { wtrans_tile(t, Wv,  Btv,  DV_, DA_, bid); return; }
    bid -= PREP_NV;
    if (bid < PREP_NQA) { wtrans_tile(t, Wqa, Btqa, DQ_, DA_, bid); return; }
    bid -= PREP_NQA;
    if (bid < PREP_NQF) { wtrans_tile(t, Wqf, Btqf, DQ_, DH_, bid); return; }
    bid -= PREP_NQF;
    if (bid < PREP_NC)  { wtrans_tile(t, Wc,  Btc,  DH_, NANS_, bid); return; }
    bid -= PREP_NC;
    if (bid < PREP_NF)  {
        int g = bid / (16 * 64);
        wtrans_tile(t, Wf + (size_t)g * DV_ * DHG_, Btf + (size_t)g * DHG_ * DV_,
                    DV_, DHG_, bid % (16 * 64));
        return;
    }
    bid -= PREP_NF;
    {
        int i = bid * 1024 + threadIdx.y * 32 + threadIdx.x;
        if (i < B_ * DQ_)
            qr[i] = to_tf32(q[i]);
    }
}

// ---------------------------------------------------------------------------
// fused scores-reduce + softmax over spatial axis, block per (b, g)
// scores[b,s,g] = ba[g] + sum_slot spart[slot, b*S+s, g]; att = softmax_s
// ---------------------------------------------------------------------------
__global__ void k_softmax(const float* __restrict__ spart,
                          const float* __restrict__ ba,
                          float* __restrict__ att)
{
    int b = blockIdx.x >> 2;
    int g = blockIdx.x & 3;
    int tid = threadIdx.x;
    __shared__ float red[256];

    float v = -1e30f;
    if (tid < S_) {
        int row = b * S_ + tid;
        float s = __ldg(ba + g);
#pragma unroll
        for (int slot = 0; slot < NSLOT_MAIN; slot++)
            s += spart[((size_t)slot * M_MAIN + row) * G_ + g];
        v = s;
    }

    red[tid] = v;
    __syncthreads();
#pragma unroll
    for (int o = 128; o; o >>= 1) {
        if (tid < o) red[tid] = fmaxf(red[tid], red[tid + o]);
        __syncthreads();
    }
    float mx = red[0];
    __syncthreads();

    float e = (tid < S_) ? expf(v - mx) : 0.f;
    red[tid] = e;
    __syncthreads();
#pragma unroll
    for (int o = 128; o; o >>= 1) {
        if (tid < o) red[tid] += red[tid + o];
        __syncthreads();
    }
    float inv = 1.f / red[0];

    if (tid < S_)
        att[(size_t)b * S_ * G_ + tid * G_ + g] = e * inv;
}

// v_att[b,g,c] = sum_s att[b,s,g] * v[b,c,s]  (tf32-rounded output)
__global__ void k_pool(const float* __restrict__ v, const float* __restrict__ att,
                       float* __restrict__ vatt)
{
    __shared__ float satt[G_][S_];
    int tid = threadIdx.x;
    int b     = blockIdx.x / (DV_ / 8);
    int cBase = (blockIdx.x % (DV_ / 8)) * 8;

    const float* ap = att + (size_t)b * S_ * G_;
    for (int i = tid; i < S_ * G_; i += 256)
        satt[i & 3][i >> 2] = ap[i];
    __syncthreads();

    int warp = tid >> 5, lane = tid & 31;
    int c = cBase + warp;
    const float* vp = v + ((size_t)b * DV_ + c) * S_;

    float a0 = 0.f, a1 = 0.f, a2 = 0.f, a3 = 0.f;
    for (int s = lane; s < S_; s += 32) {
        float x = vp[s];
        a0 = fmaf(x, satt[0][s], a0);
        a1 = fmaf(x, satt[1][s], a1);
        a2 = fmaf(x, satt[2][s], a2);
        a3 = fmaf(x, satt[3][s], a3);
    }
#pragma unroll
    for (int o = 16; o; o >>= 1) {
        a0 += __shfl_xor_sync(0xffffffff, a0, o);
        a1 += __shfl_xor_sync(0xffffffff, a1, o);
        a2 += __shfl_xor_sync(0xffffffff, a2, o);
        a3 += __shfl_xor_sync(0xffffffff, a3, o);
    }
    if (lane == 0) {
        vatt[((size_t)b * G_ + 0) * DV_ + c] = to_tf32(a0);
        vatt[((size_t)b * G_ + 1) * DV_ + c] = to_tf32(a1);
        vatt[((size_t)b * G_ + 2) * DV_ + c] = to_tf32(a2);
        vatt[((size_t)b * G_ + 3) * DV_ + c] = to_tf32(a3);
    }
}

// x_fused = tf32(tanh(xv * xqf))
__global__ void k_ewfuse(const float* __restrict__ xv, const float* __restrict__ xqf,
                         float* __restrict__ out)
{
    int i = blockIdx.x * 256 + threadIdx.x;
    if (i < B_ * DH_)
        out[i] = to_tf32(tanhf(xv[i] * xqf[i]));
}

// ---------------------------------------------------------------------------
// host launcher — MAIN GEMM deliberately at launch index 3 (ncu samples it)
// ---------------------------------------------------------------------------
extern "C" void kernel_launch(void* const* d_in, const int* in_sizes, int n_in,
                              void* d_out, int out_size)
{
    const float* input_v = (const float*)d_in[0];
    const float* x_q_vec = (const float*)d_in[1];
    const float* Wv_att  = (const float*)d_in[2];
    const float* bv_att  = (const float*)d_in[3];
    const float* Wq_att  = (const float*)d_in[4];
    const float* bq_att  = (const float*)d_in[5];
    const float* Wa      = (const float*)d_in[6];
    const float* ba      = (const float*)d_in[7];
    const float* Wf      = (const float*)d_in[8];
    const float* bf      = (const float*)d_in[9];
    const float* Wqf     = (const float*)d_in[10];
    const float* bqf     = (const float*)d_in[11];
    const float* Wc      = (const float*)d_in[12];
    const float* bc      = (const float*)d_in[13];
    float* out = (float*)d_out;

    float *At, *Btv, *Btqa, *Btqf, *Btc, *Btf, *qr, *xq_att, *spart,
          *att, *vatt, *xv, *xqf, *xfused;
    cudaGetSymbolAddress((void**)&At,     g_At);
    cudaGetSymbolAddress((void**)&Btv,    g_Bt_v);
    cudaGetSymbolAddress((void**)&Btqa,   g_Bt_qatt);
    cudaGetSymbolAddress((void**)&Btqf,   g_Bt_qf);
    cudaGetSymbolAddress((void**)&Btc,    g_Bt_c);
    cudaGetSymbolAddress((void**)&Btf,    g_Bt_f);
    cudaGetSymbolAddress((void**)&qr,     g_qr);
    cudaGetSymbolAddress((void**)&xq_att, g_xq_att);
    cudaGetSymbolAddress((void**)&spart,  g_spart);
    cudaGetSymbolAddress((void**)&att,    g_att);
    cudaGetSymbolAddress((void**)&vatt,   g_vatt);
    cudaGetSymbolAddress((void**)&xv,     g_xv);
    cudaGetSymbolAddress((void**)&xqf,    g_xqf);
    cudaGetSymbolAddress((void**)&xfused, g_xfused);

    const int SMEM = 3 * 32768 + 64;   // 98368
    cudaFuncSetAttribute(k_tcgemm<0>, cudaFuncAttributeMaxDynamicSharedMemorySize, SMEM);
    cudaFuncSetAttribute(k_tcgemm<1>, cudaFuncAttributeMaxDynamicSharedMemorySize, SMEM);
    cudaFuncSetAttribute(k_tcgemm<3>, cudaFuncAttributeMaxDynamicSharedMemorySize, SMEM);

    dim3 t32(32, 32);

    // 0: fused prep (all weight transposes + q rounding)
    k_prep<<<PREP_BLOCKS, t32>>>(Wv_att, Wq_att, Wqf, Wc, Wf, x_q_vec,
                                 Btv, Btqa, Btqf, Btc, Btf, qr);

    // 1: transpose input_v -> At
    k_transpose<<<dim3(7, DV_ / 32, B_), t32>>>(input_v, At);

    // 2: xq_att = tanh(q @ Wq_att + bq_att)   [128, 1200]
    k_tcgemm<1><<<dim3(10, 1, 1), 256, SMEM>>>(
        qr, 0, DQ_, Btqa, 0, xq_att, 0, DA_, bq_att, 0,
        nullptr, nullptr, nullptr, B_, DA_, DQ_);

    // 3: MAIN fused GEMM (x_att never materialized) — ncu samples this index
    k_tcgemm<3><<<dim3(NSLOT_MAIN, M_MAIN / 128, 1), 256, SMEM>>>(
        At, 0, DV_, Btv, 0, nullptr, 0, 0, bv_att, 0,
        xq_att, Wa, spart, M_MAIN, DA_, DV_);

    // 4: fused scores-reduce + softmax over spatial
    k_softmax<<<B_ * G_, 256>>>(spart, ba, att);

    // 5: attention pooling
    k_pool<<<B_ * (DV_ / 8), 256>>>(input_v, att, vatt);

    // 6: glimpse fusion (batched over g)
    k_tcgemm<1><<<dim3(DHG_ / 128, 1, G_), 256, SMEM>>>(
        vatt, DV_, G_ * DV_, Btf, (long long)DHG_ * DV_,
        xv, DHG_, DH_, bf, DHG_,
        nullptr, nullptr, nullptr, B_, DHG_, DV_);

    // 7: xqf = tanh(q @ Wqf + bqf)   [128, 2048]
    k_tcgemm<1><<<dim3(DH_ / 128, 1, 1), 256, SMEM>>>(
        qr, 0, DQ_, Btqf, 0, xqf, 0, DH_, bqf, 0,
        nullptr, nullptr, nullptr, B_, DH_, DQ_);

    // 8: x = tf32(tanh(xv * xqf))
    k_ewfuse<<<(B_ * DH_ + 255) / 256, 256>>>(xv, xqf, xfused);

    // 9: classifier: out = x @ Wc + bc   [128, 3000]
    k_tcgemm<0><<<dim3((NANS_ + 127) / 128, 1, 1), 256, SMEM>>>(
        xfused, 0, DH_, Btc, 0, out, 0, NANS_, bc, 0,
        nullptr, nullptr, nullptr, B_, NANS_, DH_);
}